// round 12
// baseline (speedup 1.0000x reference)
#include <cuda_runtime.h>
#include <cuda_fp16.h>
#include <cstdint>

#define BH   32
#define S    2048
#define D    64
#define TQ   16
#define NT   512
#define SCP  2052            // fp32 score row stride (floats)
#define QSP  68
#define RMP  18
#define PSTR 1036            // p hi/lo row stride (u32)
#define NEG_INF_F (-1e10f)
#define SCALE     (0.125f)

// smem layout (u32 units): score region doubles as p hi/lo overlay
#define OFF_P     0            // 33152 u32
#define OFF_PLO   16576
#define OFF_QS    33152        // 1088 floats
#define OFF_RMAX  34240        // 288 floats
#define OFF_INVS  34528        // 16 floats
#define SMEM_U32  34560
#define SMEM_BYTES (SMEM_U32 * 4)

// pre-split fp16 operands in global scratch
__device__ __half g_Khi[BH * S * D];
__device__ __half g_Klo[BH * S * D];
__device__ __half g_Vthi[BH * D * S];   // transposed [bh][d][s]
__device__ __half g_Vtlo[BH * D * S];

__device__ __forceinline__ uint32_t pack_h2(float x, float y) {
    __half2 h = __floats2half2_rn(x, y);
    return *reinterpret_cast<uint32_t*>(&h);
}
__device__ __forceinline__ float2 unpack_h2(uint32_t u) {
    __half2 h = *reinterpret_cast<__half2*>(&u);
    return __half22float2(h);
}
__device__ __forceinline__ void split2(float x, float y, uint32_t& hi, uint32_t& lo) {
    hi = pack_h2(x, y);
    float2 hf = unpack_h2(hi);
    lo = pack_h2(x - hf.x, y - hf.y);
}

__device__ __forceinline__ void mma_f16(float* c, const uint32_t* a, uint32_t b0, uint32_t b1) {
    asm volatile(
        "mma.sync.aligned.m16n8k16.row.col.f32.f16.f16.f32 "
        "{%0,%1,%2,%3},{%4,%5,%6,%7},{%8,%9},{%0,%1,%2,%3};"
        : "+f"(c[0]), "+f"(c[1]), "+f"(c[2]), "+f"(c[3])
        : "r"(a[0]), "r"(a[1]), "r"(a[2]), "r"(a[3]), "r"(b0), "r"(b1));
}

// per-warp K fragment loads straight from global (L2): 8 rows x 64 halves hi+lo
__device__ __forceinline__ void load_kfrag(uint32_t* kh, uint32_t* kl,
                                           const uint32_t* rh, const uint32_t* rl,
                                           int tig) {
    #pragma unroll
    for (int c = 0; c < 4; ++c) {
        kh[c * 2]     = __ldg(rh + c * 8 + tig);
        kh[c * 2 + 1] = __ldg(rh + c * 8 + tig + 4);
        kl[c * 2]     = __ldg(rl + c * 8 + tig);
        kl[c * 2 + 1] = __ldg(rl + c * 8 + tig + 4);
    }
}

// per-warp V^T fragment loads: 4 n-groups x 2 k-positions, hi+lo
__device__ __forceinline__ void load_vfrag(uint32_t* vh, uint32_t* vl,
                                           const uint32_t* vthi, const uint32_t* vtlo,
                                           int drow0, int su, int tig) {
    #pragma unroll
    for (int nt = 0; nt < 4; ++nt) {
        const uint32_t* rh = vthi + (size_t)(drow0 + nt * 8) * (S / 2) + su;
        const uint32_t* rl = vtlo + (size_t)(drow0 + nt * 8) * (S / 2) + su;
        vh[nt * 2]     = __ldg(rh + tig);
        vh[nt * 2 + 1] = __ldg(rh + tig + 4);
        vl[nt * 2]     = __ldg(rl + tig);
        vl[nt * 2 + 1] = __ldg(rl + tig + 4);
    }
}

// ---------------- pre-kernels ----------------
__global__ void conv_k_kernel(const float* __restrict__ K) {
    int i = blockIdx.x * blockDim.x + threadIdx.x;
    float v = K[i];
    __half h = __float2half_rn(v);
    g_Khi[i] = h;
    g_Klo[i] = __float2half_rn(v - __half2float(h));
}

__global__ void conv_vt_kernel(const float* __restrict__ V) {
    __shared__ float tile[64][65];
    int bh = blockIdx.y, s0 = blockIdx.x * 64;
    int tid = threadIdx.x;
    #pragma unroll
    for (int i = 0; i < 16; ++i) {
        int r = i * 4 + (tid >> 6), d = tid & 63;
        tile[r][d] = V[((size_t)bh * S + s0 + r) * D + d];
    }
    __syncthreads();
    #pragma unroll
    for (int i = 0; i < 16; ++i) {
        int dr = i * 4 + (tid >> 6), sc_ = tid & 63;
        float v = tile[sc_][dr];
        __half h = __float2half_rn(v);
        size_t o = ((size_t)bh * D + dr) * S + s0 + sc_;
        g_Vthi[o] = h;
        g_Vtlo[o] = __float2half_rn(v - __half2float(h));
    }
}

// ---------------- main kernel ----------------
__global__ __launch_bounds__(NT, 1)
void dist_attn_kernel(const float* __restrict__ Q,
                      const float* __restrict__ dist,
                      const int* __restrict__ mask,
                      float* __restrict__ ctx,
                      float* __restrict__ attn)
{
    extern __shared__ uint32_t smu[];
    uint32_t* phi  = smu + OFF_P;
    uint32_t* plo  = smu + OFF_PLO;
    float*    sc   = (float*)(smu + OFF_P);     // fp32 scores (phases 1-2)
    float*    Qs   = (float*)(smu + OFF_QS);
    float*    rmax = (float*)(smu + OFF_RMAX);
    float*    invs = (float*)(smu + OFF_INVS);

    const int t    = threadIdx.x;
    const int warp = t >> 5;
    const int lane = t & 31;
    const int gid  = lane >> 2;
    const int tig  = lane & 3;
    const int bh = blockIdx.y;
    const int q0 = blockIdx.x * TQ;
    const size_t rowbase = (size_t)bh * S;

    const uint32_t* Khi_u = (const uint32_t*)(g_Khi + (size_t)bh * S * D);
    const uint32_t* Klo_u = (const uint32_t*)(g_Klo + (size_t)bh * S * D);

    if (t < 256) {
        const float4 v = ((const float4*)(Q + (rowbase + q0) * D))[t];
        int qr = t >> 4, d4 = t & 15;
        *(float4*)(Qs + qr * QSP + d4 * 4) = v;
    }
    __syncthreads();

    // Q A-fragments (fp16 hi/lo), 4 k16-chunks
    uint32_t qa_hi[4][4], qa_lo[4][4];
    #pragma unroll
    for (int c = 0; c < 4; ++c) {
        const float* qg  = Qs + gid * QSP       + c * 16 + 2 * tig;
        const float* qg8 = Qs + (gid + 8) * QSP + c * 16 + 2 * tig;
        split2(qg[0],  qg[1],  qa_hi[c][0], qa_lo[c][0]);
        split2(qg8[0], qg8[1], qa_hi[c][1], qa_lo[c][1]);
        split2(qg[8],  qg[9],  qa_hi[c][2], qa_lo[c][2]);
        split2(qg8[8], qg8[9], qa_hi[c][3], qa_lo[c][3]);
    }

    // ============ Phase 1: QK^T + dist/mask/scale + row-max — NO barriers ============
    const size_t rg0 = (rowbase + q0 + gid) * S;
    const size_t rg8 = (rowbase + q0 + gid + 8) * S;
    const int colw = warp * 8 + 2 * tig;
    const int krow = warp * 8 + gid;            // this warp's K row within a tile

    // register double-buffers
    uint32_t kh[2][8], kl[2][8];
    load_kfrag(kh[0], kl[0], Khi_u + krow * 32, Klo_u + krow * 32, tig);

    float2 dd0[2], dd1[2];
    int2   mm0[2], mm1[2];
    #pragma unroll
    for (int p = 0; p < 2; ++p) {
        int col = p * 128 + colw;
        dd0[p] = *(const float2*)(dist + rg0 + col);
        dd1[p] = *(const float2*)(dist + rg8 + col);
        mm0[p] = *(const int2*)(mask + rg0 + col);
        mm1[p] = *(const int2*)(mask + rg8 + col);
    }

    float m0 = -3.4e38f, m1 = -3.4e38f;
    #pragma unroll
    for (int p = 0; p < 16; ++p) {
        const int cb = p & 1;
        if (p < 15)
            load_kfrag(kh[cb ^ 1], kl[cb ^ 1],
                       Khi_u + ((p + 1) * 128 + krow) * 32,
                       Klo_u + ((p + 1) * 128 + krow) * 32, tig);

        float2 d0 = dd0[cb], d1 = dd1[cb];
        int2   k0 = mm0[cb], k1 = mm1[cb];
        if (p + 2 < 16) {
            int col = (p + 2) * 128 + colw;
            dd0[cb] = *(const float2*)(dist + rg0 + col);
            dd1[cb] = *(const float2*)(dist + rg8 + col);
            mm0[cb] = *(const int2*)(mask + rg0 + col);
            mm1[cb] = *(const int2*)(mask + rg8 + col);
        }

        float aHH[4] = {0,0,0,0}, aHL[4] = {0,0,0,0}, aLH[4] = {0,0,0,0};
        #pragma unroll
        for (int c = 0; c < 4; ++c) {
            uint32_t b0h = kh[cb][c * 2], b1h = kh[cb][c * 2 + 1];
            uint32_t b0l = kl[cb][c * 2], b1l = kl[cb][c * 2 + 1];
            mma_f16(aHH, qa_hi[c], b0h, b1h);
            mma_f16(aHL, qa_hi[c], b0l, b1l);
            mma_f16(aLH, qa_lo[c], b0h, b1h);
        }
        float s0 = aHH[0] + aHL[0] + aLH[0];
        float s1 = aHH[1] + aHL[1] + aLH[1];
        float s2 = aHH[2] + aHL[2] + aLH[2];
        float s3 = aHH[3] + aHL[3] + aLH[3];
        s0 = k0.x ? NEG_INF_F : d0.x * s0 * SCALE;
        s1 = k0.y ? NEG_INF_F : d0.y * s1 * SCALE;
        s2 = k1.x ? NEG_INF_F : d1.x * s2 * SCALE;
        s3 = k1.y ? NEG_INF_F : d1.y * s3 * SCALE;
        m0 = fmaxf(m0, fmaxf(s0, s1));
        m1 = fmaxf(m1, fmaxf(s2, s3));
        const int col = p * 128 + colw;
        *(float2*)(sc + gid * SCP + col)       = make_float2(s0, s1);
        *(float2*)(sc + (gid + 8) * SCP + col) = make_float2(s2, s3);
    }
    #pragma unroll
    for (int o = 1; o <= 2; o <<= 1) {
        m0 = fmaxf(m0, __shfl_xor_sync(0xffffffffu, m0, o));
        m1 = fmaxf(m1, __shfl_xor_sync(0xffffffffu, m1, o));
    }
    if (tig == 0) {
        rmax[warp * RMP + gid]     = m0;
        rmax[warp * RMP + gid + 8] = m1;
    }
    __syncthreads();   // barrier #1: scores complete

    // ============ Phase 2: exp + row-sum, store p as fp16 hi/lo overlay ============
    {
        const int q = warp;
        float4* scRow = (float4*)(sc + q * SCP);

        float m = (lane < 16) ? rmax[lane * RMP + q] : -3.4e38f;
        #pragma unroll
        for (int o = 16; o > 0; o >>= 1)
            m = fmaxf(m, __shfl_xor_sync(0xffffffffu, m, o));

        float4 sv[16];
        float sum = 0.f;
        #pragma unroll
        for (int i = 0; i < 16; ++i) {
            float4 s = scRow[i * 32 + lane];
            s.x = __expf(s.x - m); s.y = __expf(s.y - m);
            s.z = __expf(s.z - m); s.w = __expf(s.w - m);
            sv[i] = s;
            sum += s.x + s.y + s.z + s.w;
        }
        #pragma unroll
        for (int o = 16; o > 0; o >>= 1)
            sum += __shfl_xor_sync(0xffffffffu, sum, o);
        if (lane == 0) invs[q] = 1.f / sum;

        __syncthreads();   // barrier #2: all fp32 reads done before hi/lo overlay

        uint32_t* ph = phi + q * PSTR;
        uint32_t* pl = plo + q * PSTR;
        #pragma unroll
        for (int i = 0; i < 16; ++i) {
            float4 s = sv[i];
            uint32_t h0, l0, h1, l1;
            split2(s.x, s.y, h0, l0);
            split2(s.z, s.w, h1, l1);
            int pb = i * 64 + lane * 2;
            *(uint2*)(ph + pb) = make_uint2(h0, h1);
            *(uint2*)(pl + pb) = make_uint2(l0, l1);
        }
    }
    __syncthreads();   // barrier #3: p overlay complete

    // ============ Phase 3: p @ V (8-way split-k x 2-way n) + attn write — NO barriers ============
    {
        const int kg = warp & 7;
        const int nh = warp >> 3;
        const int drow0 = nh * 32 + gid;
        const float invW = invs[warp];
        float4* attnRowW = (float4*)(attn + (rowbase + q0 + warp) * S);

        const uint32_t* Vthi_u = (const uint32_t*)(g_Vthi + (size_t)bh * D * S);
        const uint32_t* Vtlo_u = (const uint32_t*)(g_Vtlo + (size_t)bh * D * S);

        uint32_t vh[2][8], vl[2][8];
        load_vfrag(vh[0], vl[0], Vthi_u, Vtlo_u, drow0, kg * 8, tig);

        float acc[4][4];
        #pragma unroll
        for (int i = 0; i < 4; ++i)
            #pragma unroll
            for (int j = 0; j < 4; ++j) acc[i][j] = 0.f;

        #pragma unroll
        for (int p = 0; p < 16; ++p) {
            const int cb = p & 1;
            if (p < 15)
                load_vfrag(vh[cb ^ 1], vl[cb ^ 1], Vthi_u, Vtlo_u,
                           drow0, ((p + 1) * 128 + kg * 16) / 2, tig);

            // coalesced attn chunk: warp w writes row w, tile's 128 cols
            {
                int pb = p * 64 + lane * 2;
                uint2 h = *(const uint2*)(phi + warp * PSTR + pb);
                uint2 l = *(const uint2*)(plo + warp * PSTR + pb);
                float2 ha = unpack_h2(h.x), la = unpack_h2(l.x);
                float2 hb = unpack_h2(h.y), lb = unpack_h2(l.y);
                attnRowW[p * 32 + lane] = make_float4(
                    (ha.x + la.x) * invW, (ha.y + la.y) * invW,
                    (hb.x + lb.x) * invW, (hb.y + lb.y) * invW);
            }

            // A fragments from p hi/lo overlay
            const int pb = p * 64 + kg * 8 + tig;
            uint32_t Ah[4], Al[4];
            Ah[0] = phi[gid * PSTR + pb];
            Ah[1] = phi[(gid + 8) * PSTR + pb];
            Ah[2] = phi[gid * PSTR + pb + 4];
            Ah[3] = phi[(gid + 8) * PSTR + pb + 4];
            Al[0] = plo[gid * PSTR + pb];
            Al[1] = plo[(gid + 8) * PSTR + pb];
            Al[2] = plo[gid * PSTR + pb + 4];
            Al[3] = plo[(gid + 8) * PSTR + pb + 4];

            #pragma unroll
            for (int nt = 0; nt < 4; ++nt) {
                uint32_t b0h = vh[cb][nt * 2], b1h = vh[cb][nt * 2 + 1];
                uint32_t b0l = vl[cb][nt * 2], b1l = vl[cb][nt * 2 + 1];
                mma_f16(acc[nt], Ah, b0h, b1h);
                mma_f16(acc[nt], Ah, b0l, b1l);
                mma_f16(acc[nt], Al, b0h, b1h);
            }
        }
        __syncthreads();   // barrier #4: all p reads done; reuse score region as scratch

        // split-k reduce: red[kg 8][q 16][68]
        float* red = (float*)smu;
        #pragma unroll
        for (int nt = 0; nt < 4; ++nt) {
            int d = nh * 32 + nt * 8 + 2 * tig;
            *(float2*)(red + kg * 1088 + gid * 68 + d) =
                make_float2(acc[nt][0], acc[nt][1]);
            *(float2*)(red + kg * 1088 + (gid + 8) * 68 + d) =
                make_float2(acc[nt][2], acc[nt][3]);
        }
        __syncthreads();   // barrier #5

        #pragma unroll
        for (int o = t; o < TQ * D; o += NT) {
            int q = o >> 6, d = o & 63;
            float s = 0.f;
            #pragma unroll
            for (int g = 0; g < 8; ++g)
                s += red[g * 1088 + q * 68 + d];
            ctx[(rowbase + q0 + q) * D + d] = s * invs[q];
        }
    }
}

extern "C" void kernel_launch(void* const* d_in, const int* in_sizes, int n_in,
                              void* d_out, int out_size)
{
    const float* Q    = (const float*)d_in[0];
    const float* K    = (const float*)d_in[1];
    const float* V    = (const float*)d_in[2];
    const float* dist = (const float*)d_in[3];
    const int*   mask = (const int*)d_in[4];

    float* ctx  = (float*)d_out;
    float* attn = (float*)d_out + (size_t)BH * S * D;

    conv_k_kernel<<<(BH * S * D) / 256, 256>>>(K);
    {
        dim3 g(S / 64, BH);
        conv_vt_kernel<<<g, 256>>>(V);
    }

    cudaFuncSetAttribute(dist_attn_kernel,
                         cudaFuncAttributeMaxDynamicSharedMemorySize,
                         SMEM_BYTES);

    dim3 grid(S / TQ, BH);
    dist_attn_kernel<<<grid, NT, SMEM_BYTES>>>(Q, dist, mask, ctx, attn);
}

// round 13
// speedup vs baseline: 1.0108x; 1.0108x over previous
#include <cuda_runtime.h>
#include <cuda_fp16.h>
#include <cstdint>

#define BH   32
#define S    2048
#define D    64
#define TQ   8
#define NT   256
#define SCP  2052            // fp32 score row stride (floats)
#define QSP  68
#define PSTR 1036            // p hi/lo row stride (u32)
#define NTILES 32            // 64-row tiles
#define NEG_INF_F (-1e10f)
#define SCALE     (0.125f)

// smem layout (u32 units)
#define OFF_P     0            // fp32 scores 8x2052 (16416) / p hi+lo overlay (16576)
#define OFF_PLO   8288
#define OFF_BUFA  16576        // tile buffer A (4608 u32: hi 2304 + lo 2304)
#define OFF_BUFB  21184
#define OFF_QS    25792        // 8x68 floats
#define OFF_RMAX  26336        // 8 warps x 12
#define OFF_INVS  26432        // 8
#define SMEM_U32  26448
#define SMEM_BYTES (SMEM_U32 * 4)

#define KSTR 36                // tile row stride (u32)
#define KLO  2304              // lo offset within tile buffer

// pre-split fp16 operands in global scratch
__device__ __half g_Khi[BH * S * D];
__device__ __half g_Klo[BH * S * D];
__device__ __half g_Vthi[BH * D * S];   // transposed [bh][d][s]
__device__ __half g_Vtlo[BH * D * S];

__device__ __forceinline__ uint32_t pack_h2(float x, float y) {
    __half2 h = __floats2half2_rn(x, y);
    return *reinterpret_cast<uint32_t*>(&h);
}
__device__ __forceinline__ float2 unpack_h2(uint32_t u) {
    __half2 h = *reinterpret_cast<__half2*>(&u);
    return __half22float2(h);
}
__device__ __forceinline__ void split2(float x, float y, uint32_t& hi, uint32_t& lo) {
    hi = pack_h2(x, y);
    float2 hf = unpack_h2(hi);
    lo = pack_h2(x - hf.x, y - hf.y);
}

__device__ __forceinline__ void mma_f16(float* c, const uint32_t* a, uint32_t b0, uint32_t b1) {
    asm volatile(
        "mma.sync.aligned.m16n8k16.row.col.f32.f16.f16.f32 "
        "{%0,%1,%2,%3},{%4,%5,%6,%7},{%8,%9},{%0,%1,%2,%3};"
        : "+f"(c[0]), "+f"(c[1]), "+f"(c[2]), "+f"(c[3])
        : "r"(a[0]), "r"(a[1]), "r"(a[2]), "r"(a[3]), "r"(b0), "r"(b1));
}

__device__ __forceinline__ void cpa16(void* dst, const void* src) {
    uint32_t d = (uint32_t)__cvta_generic_to_shared(dst);
    asm volatile("cp.async.cg.shared.global [%0], [%1], 16;" :: "r"(d), "l"(src));
}
__device__ __forceinline__ void cp_commit() { asm volatile("cp.async.commit_group;"); }
__device__ __forceinline__ void cp_wait_all() { asm volatile("cp.async.wait_group 0;" ::: "memory"); }

// K tile: 64 rows x 64 fp16 hi + lo (16KB)
__device__ __forceinline__ void cp_ktile(const __half* khi, const __half* klo,
                                         uint32_t* buf, int t) {
    #pragma unroll
    for (int i = 0; i < 4; ++i) {
        int idx = t + i * NT;           // 0..1023
        int half = idx >> 9;
        int cidx = idx & 511;
        int r = cidx >> 3, off = cidx & 7;
        const __half* src = (half ? klo : khi) + r * 64 + off * 8;
        uint32_t* dst = buf + half * KLO + r * KSTR + off * 4;
        cpa16(dst, src);
    }
    cp_commit();
}

// V^T tile: 64 d-rows x 64 fp16 (cols pcol..pcol+63), hi + lo
__device__ __forceinline__ void cp_vtile(const __half* vhi, const __half* vlo,
                                         uint32_t* buf, int t, int pcol) {
    #pragma unroll
    for (int i = 0; i < 4; ++i) {
        int idx = t + i * NT;
        int half = idx >> 9;
        int cidx = idx & 511;
        int r = cidx >> 3, off = cidx & 7;
        const __half* src = (half ? vlo : vhi) + (size_t)r * S + pcol + off * 8;
        uint32_t* dst = buf + half * KLO + r * KSTR + off * 4;
        cpa16(dst, src);
    }
    cp_commit();
}

// ---------------- pre-kernels ----------------
__global__ void conv_k_kernel(const float* __restrict__ K) {
    int i = blockIdx.x * blockDim.x + threadIdx.x;
    float v = K[i];
    __half h = __float2half_rn(v);
    g_Khi[i] = h;
    g_Klo[i] = __float2half_rn(v - __half2float(h));
}

__global__ void conv_vt_kernel(const float* __restrict__ V) {
    __shared__ float tile[64][65];
    int bh = blockIdx.y, s0 = blockIdx.x * 64;
    int tid = threadIdx.x;
    #pragma unroll
    for (int i = 0; i < 16; ++i) {
        int r = i * 4 + (tid >> 6), d = tid & 63;
        tile[r][d] = V[((size_t)bh * S + s0 + r) * D + d];
    }
    __syncthreads();
    #pragma unroll
    for (int i = 0; i < 16; ++i) {
        int dr = i * 4 + (tid >> 6), sc_ = tid & 63;
        float v = tile[sc_][dr];
        __half h = __float2half_rn(v);
        size_t o = ((size_t)bh * D + dr) * S + s0 + sc_;
        g_Vthi[o] = h;
        g_Vtlo[o] = __float2half_rn(v - __half2float(h));
    }
}

// ---------------- main kernel ----------------
__global__ __launch_bounds__(NT, 2)
void dist_attn_kernel(const float* __restrict__ Q,
                      const float* __restrict__ dist,
                      const int* __restrict__ mask,
                      float* __restrict__ ctx,
                      float* __restrict__ attn)
{
    extern __shared__ uint32_t smu[];
    uint32_t* phi  = smu + OFF_P;
    uint32_t* plo  = smu + OFF_PLO;
    float*    sc   = (float*)(smu + OFF_P);     // fp32 scores (phases 1-2)
    uint32_t* bufA = smu + OFF_BUFA;
    uint32_t* bufB = smu + OFF_BUFB;
    float*    Qs   = (float*)(smu + OFF_QS);
    float*    rmax = (float*)(smu + OFF_RMAX);
    float*    invs = (float*)(smu + OFF_INVS);

    const int t    = threadIdx.x;
    const int warp = t >> 5;
    const int lane = t & 31;
    const int gid  = lane >> 2;
    const int tig  = lane & 3;
    const int bh = blockIdx.y;
    const int q0 = blockIdx.x * TQ;
    const size_t rowbase = (size_t)bh * S;

    const __half* Khi_b = g_Khi + (size_t)bh * S * D;
    const __half* Klo_b = g_Klo + (size_t)bh * S * D;

    cp_ktile(Khi_b, Klo_b, bufA, t);

    if (t < 128) {                       // Q tile: 8x64 = 128 float4
        const float4 v = ((const float4*)(Q + (rowbase + q0) * D))[t];
        int qr = t >> 4, d4 = t & 15;
        *(float4*)(Qs + qr * QSP + d4 * 4) = v;
    }
    __syncthreads();

    // Q A-fragments, hi stacked in rows 0-7, lo in rows 8-15
    uint32_t qa[4][4];
    #pragma unroll
    for (int c = 0; c < 4; ++c) {
        const float* qg = Qs + gid * QSP + c * 16 + 2 * tig;
        split2(qg[0], qg[1], qa[c][0], qa[c][1]);   // a0=hi, a1=lo (row gid+8 slot)
        split2(qg[8], qg[9], qa[c][2], qa[c][3]);
    }

    // ============ Phase 1: QK^T (4-term, 2 MMA/chunk) + dist/mask/scale + row-max ============
    const size_t rg0 = (rowbase + q0 + gid) * S;
    const int colw = warp * 8 + 2 * tig;

    float2 dd[2];
    int2   mm[2];
    #pragma unroll
    for (int p = 0; p < 2; ++p) {
        dd[p] = *(const float2*)(dist + rg0 + p * 64 + colw);
        mm[p] = *(const int2*)(mask + rg0 + p * 64 + colw);
    }

    float m0 = -3.4e38f;
    #pragma unroll
    for (int p = 0; p < NTILES; ++p) {
        const int cb = p & 1;
        uint32_t* cur = cb ? bufB : bufA;
        uint32_t* nxt = cb ? bufA : bufB;

        float2 d0 = dd[cb];
        int2   k0 = mm[cb];
        if (p + 2 < NTILES) {
            dd[cb] = *(const float2*)(dist + rg0 + (p + 2) * 64 + colw);
            mm[cb] = *(const int2*)(mask + rg0 + (p + 2) * 64 + colw);
        }

        cp_wait_all();
        __syncthreads();
        if (p < NTILES - 1)
            cp_ktile(Khi_b + (p + 1) * 64 * D, Klo_b + (p + 1) * 64 * D, nxt, t);

        float accA[4] = {0,0,0,0}, accB[4] = {0,0,0,0};
        const uint32_t* kb = cur + (warp * 8 + gid) * KSTR + tig;
        #pragma unroll
        for (int c = 0; c < 4; ++c) {
            uint32_t b0h = kb[c * 8],       b1h = kb[c * 8 + 4];
            uint32_t b0l = kb[KLO + c * 8], b1l = kb[KLO + c * 8 + 4];
            mma_f16(accA, qa[c], b0h, b1h);   // top: hi*hi, bottom: lo*hi
            mma_f16(accB, qa[c], b0l, b1l);   // top: hi*lo, bottom: lo*lo
        }
        float s0 = accA[0] + accA[2] + accB[0] + accB[2];
        float s1 = accA[1] + accA[3] + accB[1] + accB[3];
        s0 = k0.x ? NEG_INF_F : d0.x * s0 * SCALE;
        s1 = k0.y ? NEG_INF_F : d0.y * s1 * SCALE;
        m0 = fmaxf(m0, fmaxf(s0, s1));
        *(float2*)(sc + gid * SCP + p * 64 + colw) = make_float2(s0, s1);
    }
    #pragma unroll
    for (int o = 1; o <= 2; o <<= 1)
        m0 = fmaxf(m0, __shfl_xor_sync(0xffffffffu, m0, o));
    if (tig == 0) rmax[warp * 12 + gid] = m0;
    __syncthreads();   // barrier #1: scores complete

    // prefetch V^T tile 0 (overlaps softmax)
    const __half* Vthi_b = g_Vthi + (size_t)bh * D * S;
    const __half* Vtlo_b = g_Vtlo + (size_t)bh * D * S;
    cp_vtile(Vthi_b, Vtlo_b, bufA, t, 0);

    // ============ Phase 2: exp + row-sum, store p as fp16 hi/lo overlay ============
    {
        const int q = warp;          // 8 warps, 8 rows
        float4* scRow = (float4*)(sc + q * SCP);

        float m = (lane < 8) ? rmax[lane * 12 + q] : -3.4e38f;
        #pragma unroll
        for (int o = 16; o > 0; o >>= 1)
            m = fmaxf(m, __shfl_xor_sync(0xffffffffu, m, o));

        float4 sv[16];
        float sum = 0.f;
        #pragma unroll
        for (int i = 0; i < 16; ++i) {
            float4 s = scRow[i * 32 + lane];
            s.x = __expf(s.x - m); s.y = __expf(s.y - m);
            s.z = __expf(s.z - m); s.w = __expf(s.w - m);
            sv[i] = s;
            sum += s.x + s.y + s.z + s.w;
        }
        #pragma unroll
        for (int o = 16; o > 0; o >>= 1)
            sum += __shfl_xor_sync(0xffffffffu, sum, o);
        if (lane == 0) invs[q] = 1.f / sum;

        __syncthreads();   // barrier #2: fp32 reads done before overlay writes

        uint32_t* ph = phi + q * PSTR;
        uint32_t* pl = plo + q * PSTR;
        #pragma unroll
        for (int i = 0; i < 16; ++i) {
            float4 s = sv[i];
            uint32_t h0, l0, h1, l1;
            split2(s.x, s.y, h0, l0);
            split2(s.z, s.w, h1, l1);
            int pb = i * 64 + lane * 2;
            *(uint2*)(ph + pb) = make_uint2(h0, h1);
            *(uint2*)(pl + pb) = make_uint2(l0, l1);
        }
    }
    __syncthreads();   // barrier #3: p overlay complete

    // ============ Phase 3: p @ V (4-way split-k x 2-way n) + coalesced attn write ============
    {
        const int kg = warp & 3;     // k16 chunk within 64-row tile
        const int nh = warp >> 2;    // d half
        const float invW = invs[warp];
        float4* attnRowW = (float4*)(attn + (rowbase + q0 + warp) * S);

        float accA[4][4], accB[4][4];
        #pragma unroll
        for (int i = 0; i < 4; ++i)
            #pragma unroll
            for (int j = 0; j < 4; ++j) { accA[i][j] = 0.f; accB[i][j] = 0.f; }

        #pragma unroll
        for (int p = 0; p < NTILES; ++p) {
            const int cb = p & 1;
            uint32_t* cur = cb ? bufB : bufA;
            uint32_t* nxt = cb ? bufA : bufB;
            cp_wait_all();
            __syncthreads();
            if (p < NTILES - 1)
                cp_vtile(Vthi_b, Vtlo_b, nxt, t, (p + 1) * 64);

            // coalesced attn chunk: warp w writes row w, this tile's 64 cols
            if (lane < 16) {
                int pb = p * 32 + lane * 2;
                uint2 h = *(const uint2*)(phi + warp * PSTR + pb);
                uint2 l = *(const uint2*)(plo + warp * PSTR + pb);
                float2 ha = unpack_h2(h.x), la = unpack_h2(l.x);
                float2 hb = unpack_h2(h.y), lb = unpack_h2(l.y);
                attnRowW[p * 16 + lane] = make_float4(
                    (ha.x + la.x) * invW, (ha.y + la.y) * invW,
                    (hb.x + lb.x) * invW, (hb.y + lb.y) * invW);
            }

            // A fragments: hi rows 0-7, lo rows 8-15
            const int pb = p * 32 + kg * 8 + tig;
            uint32_t A[4];
            A[0] = phi[gid * PSTR + pb];
            A[1] = plo[gid * PSTR + pb];
            A[2] = phi[gid * PSTR + pb + 4];
            A[3] = plo[gid * PSTR + pb + 4];

            #pragma unroll
            for (int nt = 0; nt < 4; ++nt) {
                const uint32_t* vb = cur + (nh * 32 + nt * 8 + gid) * KSTR + kg * 8 + tig;
                uint32_t b0h = vb[0],   b1h = vb[4];
                uint32_t b0l = vb[KLO], b1l = vb[KLO + 4];
                mma_f16(accA[nt], A, b0h, b1h);
                mma_f16(accB[nt], A, b0l, b1l);
            }
        }
        __syncthreads();   // barrier #4: p reads done; reuse buffers as scratch

        // split-k reduce: red[kg 4][q 8][68]
        float* red = (float*)bufA;
        #pragma unroll
        for (int nt = 0; nt < 4; ++nt) {
            int d = nh * 32 + nt * 8 + 2 * tig;
            float o0 = accA[nt][0] + accA[nt][2] + accB[nt][0] + accB[nt][2];
            float o1 = accA[nt][1] + accA[nt][3] + accB[nt][1] + accB[nt][3];
            *(float2*)(red + kg * 544 + gid * 68 + d) = make_float2(o0, o1);
        }
        __syncthreads();   // barrier #5

        #pragma unroll
        for (int o = t; o < TQ * D; o += NT) {
            int q = o >> 6, d = o & 63;
            float s = 0.f;
            #pragma unroll
            for (int g = 0; g < 4; ++g)
                s += red[g * 544 + q * 68 + d];
            ctx[(rowbase + q0 + q) * D + d] = s * invs[q];
        }
    }
}

extern "C" void kernel_launch(void* const* d_in, const int* in_sizes, int n_in,
                              void* d_out, int out_size)
{
    const float* Q    = (const float*)d_in[0];
    const float* K    = (const float*)d_in[1];
    const float* V    = (const float*)d_in[2];
    const float* dist = (const float*)d_in[3];
    const int*   mask = (const int*)d_in[4];

    float* ctx  = (float*)d_out;
    float* attn = (float*)d_out + (size_t)BH * S * D;

    conv_k_kernel<<<(BH * S * D) / 256, 256>>>(K);
    {
        dim3 g(S / 64, BH);
        conv_vt_kernel<<<g, 256>>>(V);
    }

    cudaFuncSetAttribute(dist_attn_kernel,
                         cudaFuncAttributeMaxDynamicSharedMemorySize,
                         SMEM_BYTES);

    dim3 grid(S / TQ, BH);
    dist_attn_kernel<<<grid, NT, SMEM_BYTES>>>(Q, dist, mask, ctx, attn);
}

// round 14
// speedup vs baseline: 1.3456x; 1.3312x over previous
#include <cuda_runtime.h>
#include <cuda_fp16.h>
#include <cstdint>

#define BH   32
#define S    2048
#define D    64
#define TQ   16
#define NT   512
#define SCP  2052            // fp32 score row stride (floats)
#define QSP  68
#define RMP  18
#define PSTR 1036            // p hi/lo row stride (u32), 1036 % 32 == 12 (conflict-free)
#define NTILES 16            // 128-row tiles
#define NEG_INF_F (-1e10f)
#define SCALE     (0.125f)

// smem layout (u32 units)
#define OFF_P     0            // fp32 scores 16x2052 / p hi+lo overlay (33152 u32)
#define OFF_PLO   16576
#define OFF_KW    33152        // per-warp slice buffers: 16 warps x 2 stages x 576 u32
#define OFF_QS    51584        // 16x68 floats
#define OFF_RMAX  52672        // 16x18
#define OFF_INVS  52960        // 16
#define SMEM_U32  52976
#define SMEM_BYTES (SMEM_U32 * 4)

#define WBUF_STRIDE 1152       // per-warp: 2 stages x 576
#define STG 576                // per-stage: hi 288 + lo 288
#define LOF 288                // lo offset within stage

// pre-split fp16 operands in global scratch
__device__ __half g_Khi[BH * S * D];
__device__ __half g_Klo[BH * S * D];
__device__ __half g_Vthi[BH * D * S];   // transposed [bh][d][s]
__device__ __half g_Vtlo[BH * D * S];

__device__ __forceinline__ uint32_t pack_h2(float x, float y) {
    __half2 h = __floats2half2_rn(x, y);
    return *reinterpret_cast<uint32_t*>(&h);
}
__device__ __forceinline__ float2 unpack_h2(uint32_t u) {
    __half2 h = *reinterpret_cast<__half2*>(&u);
    return __half22float2(h);
}
__device__ __forceinline__ void split2(float x, float y, uint32_t& hi, uint32_t& lo) {
    hi = pack_h2(x, y);
    float2 hf = unpack_h2(hi);
    lo = pack_h2(x - hf.x, y - hf.y);
}

__device__ __forceinline__ void mma_f16(float* c, const uint32_t* a, uint32_t b0, uint32_t b1) {
    asm volatile(
        "mma.sync.aligned.m16n8k16.row.col.f32.f16.f16.f32 "
        "{%0,%1,%2,%3},{%4,%5,%6,%7},{%8,%9},{%0,%1,%2,%3};"
        : "+f"(c[0]), "+f"(c[1]), "+f"(c[2]), "+f"(c[3])
        : "r"(a[0]), "r"(a[1]), "r"(a[2]), "r"(a[3]), "r"(b0), "r"(b1));
}

__device__ __forceinline__ void cpa16(uint32_t* dst, const void* src) {
    uint32_t d = (uint32_t)__cvta_generic_to_shared(dst);
    asm volatile("cp.async.cg.shared.global [%0], [%1], 16;" :: "r"(d), "l"(src));
}
__device__ __forceinline__ void cp_commit() { asm volatile("cp.async.commit_group;"); }
__device__ __forceinline__ void cp_wait1() { asm volatile("cp.async.wait_group 1;" ::: "memory"); }
__device__ __forceinline__ void cp_wait0() { asm volatile("cp.async.wait_group 0;" ::: "memory"); }

// ---------------- pre-kernels ----------------
__global__ void conv_k_kernel(const float* __restrict__ K) {
    int i = blockIdx.x * blockDim.x + threadIdx.x;
    float v = K[i];
    __half h = __float2half_rn(v);
    g_Khi[i] = h;
    g_Klo[i] = __float2half_rn(v - __half2float(h));
}

__global__ void conv_vt_kernel(const float* __restrict__ V) {
    __shared__ float tile[64][65];
    int bh = blockIdx.y, s0 = blockIdx.x * 64;
    int tid = threadIdx.x;
    #pragma unroll
    for (int i = 0; i < 16; ++i) {
        int r = i * 4 + (tid >> 6), d = tid & 63;
        tile[r][d] = V[((size_t)bh * S + s0 + r) * D + d];
    }
    __syncthreads();
    #pragma unroll
    for (int i = 0; i < 16; ++i) {
        int dr = i * 4 + (tid >> 6), sc_ = tid & 63;
        float v = tile[sc_][dr];
        __half h = __float2half_rn(v);
        size_t o = ((size_t)bh * D + dr) * S + s0 + sc_;
        g_Vthi[o] = h;
        g_Vtlo[o] = __float2half_rn(v - __half2float(h));
    }
}

// ---------------- main kernel ----------------
__global__ __launch_bounds__(NT, 1)
void dist_attn_kernel(const float* __restrict__ Q,
                      const float* __restrict__ dist,
                      const int* __restrict__ mask,
                      float* __restrict__ ctx,
                      float* __restrict__ attn)
{
    extern __shared__ uint32_t smu[];
    uint32_t* phi  = smu + OFF_P;
    uint32_t* plo  = smu + OFF_PLO;
    float*    sc   = (float*)(smu + OFF_P);     // fp32 scores (phases 1-2)
    float*    Qs   = (float*)(smu + OFF_QS);
    float*    rmax = (float*)(smu + OFF_RMAX);
    float*    invs = (float*)(smu + OFF_INVS);

    const int t    = threadIdx.x;
    const int warp = t >> 5;
    const int lane = t & 31;
    const int gid  = lane >> 2;
    const int tig  = lane & 3;
    const int bh = blockIdx.y;
    const int q0 = blockIdx.x * TQ;
    const size_t rowbase = (size_t)bh * S;

    uint32_t* wbuf = smu + OFF_KW + warp * WBUF_STRIDE;   // this warp's private slices

    const __half* Khi_b = g_Khi + (size_t)bh * S * D;
    const __half* Klo_b = g_Klo + (size_t)bh * S * D;

    // --- per-warp K slice loader: 8 rows x 64 halves, hi+lo, for one tile ---
    auto load_k_slice = [&](int stage, int tile) {
        uint32_t* dst = wbuf + stage * STG;
        #pragma unroll
        for (int i = 0; i < 4; ++i) {
            int idx = lane + i * 32;        // 0..127
            int h   = idx >> 6;
            int c6  = idx & 63;
            int r   = c6 >> 3, c = c6 & 7;
            const __half* src = (h ? Klo_b : Khi_b) +
                                ((tile * 128 + warp * 8 + r) * D + c * 8);
            cpa16(dst + h * LOF + r * 36 + c * 4, src);
        }
        cp_commit();
    };

    // prologue: K slices for tiles 0 and 1
    load_k_slice(0, 0);
    load_k_slice(1, 1);

    if (t < 256) {
        const float4 v = ((const float4*)(Q + (rowbase + q0) * D))[t];
        int qr = t >> 4, d4 = t & 15;
        *(float4*)(Qs + qr * QSP + d4 * 4) = v;
    }
    __syncthreads();

    // Q A-fragments (fp16 hi/lo), 4 k16-chunks
    uint32_t qa_hi[4][4], qa_lo[4][4];
    #pragma unroll
    for (int c = 0; c < 4; ++c) {
        const float* qg  = Qs + gid * QSP       + c * 16 + 2 * tig;
        const float* qg8 = Qs + (gid + 8) * QSP + c * 16 + 2 * tig;
        split2(qg[0],  qg[1],  qa_hi[c][0], qa_lo[c][0]);
        split2(qg8[0], qg8[1], qa_hi[c][1], qa_lo[c][1]);
        split2(qg[8],  qg[9],  qa_hi[c][2], qa_lo[c][2]);
        split2(qg8[8], qg8[9], qa_hi[c][3], qa_lo[c][3]);
    }

    // ============ Phase 1: QK^T + dist/mask/scale + row-max — NO block barriers ============
    const size_t rg0 = (rowbase + q0 + gid) * S;
    const size_t rg8 = (rowbase + q0 + gid + 8) * S;
    const int colw = warp * 8 + 2 * tig;

    float2 dd0[2], dd1[2];
    int2   mm0[2], mm1[2];
    #pragma unroll
    for (int p = 0; p < 2; ++p) {
        int col = p * 128 + colw;
        dd0[p] = *(const float2*)(dist + rg0 + col);
        dd1[p] = *(const float2*)(dist + rg8 + col);
        mm0[p] = *(const int2*)(mask + rg0 + col);
        mm1[p] = *(const int2*)(mask + rg8 + col);
    }

    float m0 = -3.4e38f, m1 = -3.4e38f;
    #pragma unroll
    for (int p = 0; p < NTILES; ++p) {
        const int st = p & 1;

        float2 d0 = dd0[st], d1 = dd1[st];
        int2   k0 = mm0[st], k1 = mm1[st];
        if (p + 2 < NTILES) {
            int col = (p + 2) * 128 + colw;
            dd0[st] = *(const float2*)(dist + rg0 + col);
            dd1[st] = *(const float2*)(dist + rg8 + col);
            mm0[st] = *(const int2*)(mask + rg0 + col);
            mm1[st] = *(const int2*)(mask + rg8 + col);
        }

        if (p == NTILES - 1) cp_wait0(); else cp_wait1();
        __syncwarp();

        float aHH[4] = {0,0,0,0}, aHL[4] = {0,0,0,0}, aLH[4] = {0,0,0,0};
        const uint32_t* kb = wbuf + st * STG + gid * 36 + tig;
        #pragma unroll
        for (int c = 0; c < 4; ++c) {
            uint32_t b0h = kb[c * 8],       b1h = kb[c * 8 + 4];
            uint32_t b0l = kb[LOF + c * 8], b1l = kb[LOF + c * 8 + 4];
            mma_f16(aHH, qa_hi[c], b0h, b1h);
            mma_f16(aHL, qa_hi[c], b0l, b1l);
            mma_f16(aLH, qa_lo[c], b0h, b1h);
        }
        // next-next tile into this stage (after reads)
        __syncwarp();
        if (p + 2 < NTILES) load_k_slice(st, p + 2);

        float s0 = aHH[0] + aHL[0] + aLH[0];
        float s1 = aHH[1] + aHL[1] + aLH[1];
        float s2 = aHH[2] + aHL[2] + aLH[2];
        float s3 = aHH[3] + aHL[3] + aLH[3];
        s0 = k0.x ? NEG_INF_F : d0.x * s0 * SCALE;
        s1 = k0.y ? NEG_INF_F : d0.y * s1 * SCALE;
        s2 = k1.x ? NEG_INF_F : d1.x * s2 * SCALE;
        s3 = k1.y ? NEG_INF_F : d1.y * s3 * SCALE;
        m0 = fmaxf(m0, fmaxf(s0, s1));
        m1 = fmaxf(m1, fmaxf(s2, s3));
        const int col = p * 128 + colw;
        *(float2*)(sc + gid * SCP + col)       = make_float2(s0, s1);
        *(float2*)(sc + (gid + 8) * SCP + col) = make_float2(s2, s3);
    }
    #pragma unroll
    for (int o = 1; o <= 2; o <<= 1) {
        m0 = fmaxf(m0, __shfl_xor_sync(0xffffffffu, m0, o));
        m1 = fmaxf(m1, __shfl_xor_sync(0xffffffffu, m1, o));
    }
    if (tig == 0) {
        rmax[warp * RMP + gid]     = m0;
        rmax[warp * RMP + gid + 8] = m1;
    }
    __syncthreads();   // barrier #1: scores complete

    // ============ Phase 2: exp + row-sum, store p as fp16 hi/lo overlay ============
    {
        const int q = warp;
        float4* scRow = (float4*)(sc + q * SCP);

        float m = (lane < 16) ? rmax[lane * RMP + q] : -3.4e38f;
        #pragma unroll
        for (int o = 16; o > 0; o >>= 1)
            m = fmaxf(m, __shfl_xor_sync(0xffffffffu, m, o));

        float4 sv[16];
        float sum = 0.f;
        #pragma unroll
        for (int i = 0; i < 16; ++i) {
            float4 s = scRow[i * 32 + lane];
            s.x = __expf(s.x - m); s.y = __expf(s.y - m);
            s.z = __expf(s.z - m); s.w = __expf(s.w - m);
            sv[i] = s;
            sum += s.x + s.y + s.z + s.w;
        }
        #pragma unroll
        for (int o = 16; o > 0; o >>= 1)
            sum += __shfl_xor_sync(0xffffffffu, sum, o);
        if (lane == 0) invs[q] = 1.f / sum;

        __syncthreads();   // barrier #2: fp32 reads done before overlay writes

        uint32_t* ph = phi + q * PSTR;
        uint32_t* pl = plo + q * PSTR;
        #pragma unroll
        for (int i = 0; i < 16; ++i) {
            float4 s = sv[i];
            uint32_t h0, l0, h1, l1;
            split2(s.x, s.y, h0, l0);
            split2(s.z, s.w, h1, l1);
            int pb = i * 64 + lane * 2;
            *(uint2*)(ph + pb) = make_uint2(h0, h1);
            *(uint2*)(pl + pb) = make_uint2(l0, l1);
        }
    }
    __syncthreads();   // barrier #3: p overlay complete

    // ============ Phase 3: p @ V + attn write — NO block barriers ============
    {
        const int kg = warp & 7;     // k16 chunk within 128-row tile
        const int nh = warp >> 3;    // d half
        const float invW = invs[warp];
        float4* attnRowW = (float4*)(attn + (rowbase + q0 + warp) * S);

        const __half* Vthi_b = g_Vthi + ((size_t)bh * D + nh * 32) * S;
        const __half* Vtlo_b = g_Vtlo + ((size_t)bh * D + nh * 32) * S;

        // per-warp V slice loader: 32 d-rows x 16 halves (32B), hi+lo
        auto load_v_slice = [&](int stage, int tile) {
            uint32_t* dst = wbuf + stage * STG;
            int pcol = tile * 128 + kg * 16;
            #pragma unroll
            for (int i = 0; i < 4; ++i) {
                int idx = lane + i * 32;   // 0..127
                int h   = idx >> 6;
                int c6  = idx & 63;
                int r   = c6 >> 1, c = c6 & 1;
                const __half* src = (h ? Vtlo_b : Vthi_b) + ((size_t)r * S + pcol + c * 8);
                cpa16(dst + h * LOF + (r >> 2) * 36 + (r & 3) * 8 + c * 4, src);
            }
            cp_commit();
        };

        load_v_slice(0, 0);
        load_v_slice(1, 1);

        float acc[4][4];
        #pragma unroll
        for (int i = 0; i < 4; ++i)
            #pragma unroll
            for (int j = 0; j < 4; ++j) acc[i][j] = 0.f;

        #pragma unroll
        for (int p = 0; p < NTILES; ++p) {
            const int st = p & 1;

            if (p == NTILES - 1) cp_wait0(); else cp_wait1();
            __syncwarp();

            // coalesced attn chunk: warp w writes row w, this tile's 128 cols
            {
                int pb = p * 64 + lane * 2;
                uint2 h = *(const uint2*)(phi + warp * PSTR + pb);
                uint2 l = *(const uint2*)(plo + warp * PSTR + pb);
                float2 ha = unpack_h2(h.x), la = unpack_h2(l.x);
                float2 hb = unpack_h2(h.y), lb = unpack_h2(l.y);
                attnRowW[p * 32 + lane] = make_float4(
                    (ha.x + la.x) * invW, (ha.y + la.y) * invW,
                    (hb.x + lb.x) * invW, (hb.y + lb.y) * invW);
            }

            // A fragments from p hi/lo overlay
            const int pb = p * 64 + kg * 8 + tig;
            uint32_t Ah[4], Al[4];
            Ah[0] = phi[gid * PSTR + pb];
            Ah[1] = phi[(gid + 8) * PSTR + pb];
            Ah[2] = phi[gid * PSTR + pb + 4];
            Ah[3] = phi[(gid + 8) * PSTR + pb + 4];
            Al[0] = plo[gid * PSTR + pb];
            Al[1] = plo[(gid + 8) * PSTR + pb];
            Al[2] = plo[gid * PSTR + pb + 4];
            Al[3] = plo[(gid + 8) * PSTR + pb + 4];

            const uint32_t* vs = wbuf + st * STG;
            #pragma unroll
            for (int nt = 0; nt < 4; ++nt) {
                const uint32_t* vb = vs + (nt * 2 + (gid >> 2)) * 36 + (gid & 3) * 8 + tig;
                uint32_t b0h = vb[0],   b1h = vb[4];
                uint32_t b0l = vb[LOF], b1l = vb[LOF + 4];
                mma_f16(acc[nt], Ah, b0h, b1h);
                mma_f16(acc[nt], Ah, b0l, b1l);
                mma_f16(acc[nt], Al, b0h, b1h);
            }
            __syncwarp();
            if (p + 2 < NTILES) load_v_slice(st, p + 2);
        }
        __syncthreads();   // barrier #4: reuse per-warp region as reduce scratch

        // split-k reduce: red[kg 8][q 16][68]
        float* red = (float*)(smu + OFF_KW);
        #pragma unroll
        for (int nt = 0; nt < 4; ++nt) {
            int d = nh * 32 + nt * 8 + 2 * tig;
            *(float2*)(red + kg * 1088 + gid * 68 + d) =
                make_float2(acc[nt][0], acc[nt][1]);
            *(float2*)(red + kg * 1088 + (gid + 8) * 68 + d) =
                make_float2(acc[nt][2], acc[nt][3]);
        }
        __syncthreads();   // barrier #5

        #pragma unroll
        for (int o = t; o < TQ * D; o += NT) {
            int q = o >> 6, d = o & 63;
            float s = 0.f;
            #pragma unroll
            for (int g = 0; g < 8; ++g)
                s += red[g * 1088 + q * 68 + d];
            ctx[(rowbase + q0 + q) * D + d] = s * invs[q];
        }
    }
}

extern "C" void kernel_launch(void* const* d_in, const int* in_sizes, int n_in,
                              void* d_out, int out_size)
{
    const float* Q    = (const float*)d_in[0];
    const float* K    = (const float*)d_in[1];
    const float* V    = (const float*)d_in[2];
    const float* dist = (const float*)d_in[3];
    const int*   mask = (const int*)d_in[4];

    float* ctx  = (float*)d_out;
    float* attn = (float*)d_out + (size_t)BH * S * D;

    conv_k_kernel<<<(BH * S * D) / 256, 256>>>(K);
    {
        dim3 g(S / 64, BH);
        conv_vt_kernel<<<g, 256>>>(V);
    }

    cudaFuncSetAttribute(dist_attn_kernel,
                         cudaFuncAttributeMaxDynamicSharedMemorySize,
                         SMEM_BYTES);

    dim3 grid(S / TQ, BH);
    dist_attn_kernel<<<grid, NT, SMEM_BYTES>>>(Q, dist, mask, ctx, attn);
}

// round 15
// speedup vs baseline: 1.7155x; 1.2749x over previous
#include <cuda_runtime.h>
#include <cuda_fp16.h>
#include <cstdint>

#define BH   32
#define S    2048
#define D    64
#define TQ   16
#define NT   512
#define SCP  2052            // fp32 score row stride (floats)
#define QSP  68
#define RMP  18
#define PSTR 1036            // p hi/lo row stride (u32)
#define NTILES 16            // 128-row tiles
#define NEG_INF_F (-1e10f)
#define SCALE     (0.125f)

// smem layout (u32 units)
#define OFF_P     0            // fp32 scores 16x2052 / p hi+lo overlay
#define OFF_PLO   16576
#define OFF_KW    33152        // per-warp slice buffers: 16 warps x 4 stages x 288 u32
#define OFF_QS    51584
#define OFF_RMAX  52672
#define OFF_INVS  52960
#define SMEM_U32  52976
#define SMEM_BYTES (SMEM_U32 * 4)

#define STG 288                // per-stage u32 (hi only)
#define WBUF_STRIDE 1152       // 4 stages x 288

// pre-converted fp16 operands (hi only) in global scratch
__device__ __half g_Khi[BH * S * D];
__device__ __half g_Vthi[BH * D * S];   // transposed [bh][d][s]

__device__ __forceinline__ uint32_t pack_h2(float x, float y) {
    __half2 h = __floats2half2_rn(x, y);
    return *reinterpret_cast<uint32_t*>(&h);
}
__device__ __forceinline__ float2 unpack_h2(uint32_t u) {
    __half2 h = *reinterpret_cast<__half2*>(&u);
    return __half22float2(h);
}
__device__ __forceinline__ void split2(float x, float y, uint32_t& hi, uint32_t& lo) {
    hi = pack_h2(x, y);
    float2 hf = unpack_h2(hi);
    lo = pack_h2(x - hf.x, y - hf.y);
}

__device__ __forceinline__ void mma_f16(float* c, const uint32_t* a, uint32_t b0, uint32_t b1) {
    asm volatile(
        "mma.sync.aligned.m16n8k16.row.col.f32.f16.f16.f32 "
        "{%0,%1,%2,%3},{%4,%5,%6,%7},{%8,%9},{%0,%1,%2,%3};"
        : "+f"(c[0]), "+f"(c[1]), "+f"(c[2]), "+f"(c[3])
        : "r"(a[0]), "r"(a[1]), "r"(a[2]), "r"(a[3]), "r"(b0), "r"(b1));
}

__device__ __forceinline__ void cpa16(uint32_t* dst, const void* src) {
    uint32_t d = (uint32_t)__cvta_generic_to_shared(dst);
    asm volatile("cp.async.cg.shared.global [%0], [%1], 16;" :: "r"(d), "l"(src));
}
__device__ __forceinline__ void cp_commit() { asm volatile("cp.async.commit_group;"); }
__device__ __forceinline__ void cp_wait3() { asm volatile("cp.async.wait_group 3;" ::: "memory"); }
__device__ __forceinline__ void cp_wait2() { asm volatile("cp.async.wait_group 2;" ::: "memory"); }
__device__ __forceinline__ void cp_wait1() { asm volatile("cp.async.wait_group 1;" ::: "memory"); }
__device__ __forceinline__ void cp_wait0() { asm volatile("cp.async.wait_group 0;" ::: "memory"); }

// ---------------- pre-kernels ----------------
__global__ void conv_k_kernel(const float* __restrict__ K) {
    int i = blockIdx.x * blockDim.x + threadIdx.x;
    g_Khi[i] = __float2half_rn(K[i]);
}

__global__ void conv_vt_kernel(const float* __restrict__ V) {
    __shared__ float tile[64][65];
    int bh = blockIdx.y, s0 = blockIdx.x * 64;
    int tid = threadIdx.x;
    #pragma unroll
    for (int i = 0; i < 16; ++i) {
        int r = i * 4 + (tid >> 6), d = tid & 63;
        tile[r][d] = V[((size_t)bh * S + s0 + r) * D + d];
    }
    __syncthreads();
    #pragma unroll
    for (int i = 0; i < 16; ++i) {
        int dr = i * 4 + (tid >> 6), sc_ = tid & 63;
        g_Vthi[((size_t)bh * D + dr) * S + s0 + sc_] = __float2half_rn(tile[sc_][dr]);
    }
}

// ---------------- main kernel ----------------
__global__ __launch_bounds__(NT, 1)
void dist_attn_kernel(const float* __restrict__ Q,
                      const float* __restrict__ dist,
                      const int* __restrict__ mask,
                      float* __restrict__ ctx,
                      float* __restrict__ attn)
{
    extern __shared__ uint32_t smu[];
    uint32_t* phi  = smu + OFF_P;
    uint32_t* plo  = smu + OFF_PLO;
    float*    sc   = (float*)(smu + OFF_P);
    float*    Qs   = (float*)(smu + OFF_QS);
    float*    rmax = (float*)(smu + OFF_RMAX);
    float*    invs = (float*)(smu + OFF_INVS);

    const int t    = threadIdx.x;
    const int warp = t >> 5;
    const int lane = t & 31;
    const int gid  = lane >> 2;
    const int tig  = lane & 3;
    const int bh = blockIdx.y;
    const int q0 = blockIdx.x * TQ;
    const size_t rowbase = (size_t)bh * S;

    uint32_t* wbuf = smu + OFF_KW + warp * WBUF_STRIDE;

    const __half* Khi_b = g_Khi + (size_t)bh * S * D;

    // per-warp K slice: 8 rows x 64 halves (hi), one tile -> 256 u32 + pad
    auto load_k_slice = [&](int stage, int tile) {
        uint32_t* dst = wbuf + stage * STG;
        #pragma unroll
        for (int i = 0; i < 2; ++i) {
            int idx = lane + i * 32;        // 0..63
            int r = idx >> 3, c = idx & 7;
            const __half* src = Khi_b + ((tile * 128 + warp * 8 + r) * D + c * 8);
            cpa16(dst + r * 36 + c * 4, src);
        }
        cp_commit();
    };

    // prologue: 4-deep
    load_k_slice(0, 0);
    load_k_slice(1, 1);
    load_k_slice(2, 2);
    load_k_slice(3, 3);

    if (t < 256) {
        const float4 v = ((const float4*)(Q + (rowbase + q0) * D))[t];
        int qr = t >> 4, d4 = t & 15;
        *(float4*)(Qs + qr * QSP + d4 * 4) = v;
    }
    __syncthreads();

    // Q A-fragments (fp16 hi/lo), 4 k16-chunks
    uint32_t qa_hi[4][4], qa_lo[4][4];
    #pragma unroll
    for (int c = 0; c < 4; ++c) {
        const float* qg  = Qs + gid * QSP       + c * 16 + 2 * tig;
        const float* qg8 = Qs + (gid + 8) * QSP + c * 16 + 2 * tig;
        split2(qg[0],  qg[1],  qa_hi[c][0], qa_lo[c][0]);
        split2(qg8[0], qg8[1], qa_hi[c][1], qa_lo[c][1]);
        split2(qg[8],  qg[9],  qa_hi[c][2], qa_lo[c][2]);
        split2(qg8[8], qg8[9], qa_hi[c][3], qa_lo[c][3]);
    }

    // ============ Phase 1: QK^T (2-term) + dist/mask/scale + row-max — no block barriers ============
    const size_t rg0 = (rowbase + q0 + gid) * S;
    const size_t rg8 = (rowbase + q0 + gid + 8) * S;
    const int colw = warp * 8 + 2 * tig;

    float2 dd0[2], dd1[2];
    int2   mm0[2], mm1[2];
    #pragma unroll
    for (int p = 0; p < 2; ++p) {
        int col = p * 128 + colw;
        dd0[p] = *(const float2*)(dist + rg0 + col);
        dd1[p] = *(const float2*)(dist + rg8 + col);
        mm0[p] = *(const int2*)(mask + rg0 + col);
        mm1[p] = *(const int2*)(mask + rg8 + col);
    }

    float m0 = -3.4e38f, m1 = -3.4e38f;
    #pragma unroll
    for (int p = 0; p < NTILES; ++p) {
        const int st = p & 3;
        const int rp = p & 1;

        float2 d0 = dd0[rp], d1 = dd1[rp];
        int2   k0 = mm0[rp], k1 = mm1[rp];
        if (p + 2 < NTILES) {
            int col = (p + 2) * 128 + colw;
            dd0[rp] = *(const float2*)(dist + rg0 + col);
            dd1[rp] = *(const float2*)(dist + rg8 + col);
            mm0[rp] = *(const int2*)(mask + rg0 + col);
            mm1[rp] = *(const int2*)(mask + rg8 + col);
        }

        if      (p < NTILES - 3)  cp_wait3();
        else if (p == NTILES - 3) cp_wait2();
        else if (p == NTILES - 2) cp_wait1();
        else                      cp_wait0();
        __syncwarp();

        float aHH[4] = {0,0,0,0}, aLH[4] = {0,0,0,0};
        const uint32_t* kb = wbuf + st * STG + gid * 36 + tig;
        #pragma unroll
        for (int c = 0; c < 4; ++c) {
            uint32_t b0h = kb[c * 8], b1h = kb[c * 8 + 4];
            mma_f16(aHH, qa_hi[c], b0h, b1h);
            mma_f16(aLH, qa_lo[c], b0h, b1h);
        }
        __syncwarp();
        if (p + 4 < NTILES) load_k_slice(st, p + 4);

        float s0 = aHH[0] + aLH[0];
        float s1 = aHH[1] + aLH[1];
        float s2 = aHH[2] + aLH[2];
        float s3 = aHH[3] + aLH[3];
        s0 = k0.x ? NEG_INF_F : d0.x * s0 * SCALE;
        s1 = k0.y ? NEG_INF_F : d0.y * s1 * SCALE;
        s2 = k1.x ? NEG_INF_F : d1.x * s2 * SCALE;
        s3 = k1.y ? NEG_INF_F : d1.y * s3 * SCALE;
        m0 = fmaxf(m0, fmaxf(s0, s1));
        m1 = fmaxf(m1, fmaxf(s2, s3));
        const int col = p * 128 + colw;
        *(float2*)(sc + gid * SCP + col)       = make_float2(s0, s1);
        *(float2*)(sc + (gid + 8) * SCP + col) = make_float2(s2, s3);
    }
    #pragma unroll
    for (int o = 1; o <= 2; o <<= 1) {
        m0 = fmaxf(m0, __shfl_xor_sync(0xffffffffu, m0, o));
        m1 = fmaxf(m1, __shfl_xor_sync(0xffffffffu, m1, o));
    }
    if (tig == 0) {
        rmax[warp * RMP + gid]     = m0;
        rmax[warp * RMP + gid + 8] = m1;
    }

    // V^T slice prefetch for tiles 0..3 — overlaps the whole softmax phase
    const int kg = warp & 7;
    const int nh = warp >> 3;
    const __half* Vthi_b = g_Vthi + ((size_t)bh * D + nh * 32) * S;
    auto load_v_slice = [&](int stage, int tile) {
        uint32_t* dst = wbuf + stage * STG;
        int pcol = tile * 128 + kg * 16;
        #pragma unroll
        for (int i = 0; i < 2; ++i) {
            int idx = lane + i * 32;   // 0..63
            int r = idx >> 1, c = idx & 1;
            const __half* src = Vthi_b + ((size_t)r * S + pcol + c * 8);
            cpa16(dst + (r >> 2) * 36 + (r & 3) * 8 + c * 4, src);
        }
        cp_commit();
    };
    load_v_slice(0, 0);
    load_v_slice(1, 1);
    load_v_slice(2, 2);
    load_v_slice(3, 3);

    __syncthreads();   // barrier #1: scores complete

    // ============ Phase 2: exp + row-sum, store p as fp16 hi/lo overlay ============
    {
        const int q = warp;
        float4* scRow = (float4*)(sc + q * SCP);

        float m = (lane < 16) ? rmax[lane * RMP + q] : -3.4e38f;
        #pragma unroll
        for (int o = 16; o > 0; o >>= 1)
            m = fmaxf(m, __shfl_xor_sync(0xffffffffu, m, o));

        float4 sv[16];
        float sum = 0.f;
        #pragma unroll
        for (int i = 0; i < 16; ++i) {
            float4 s = scRow[i * 32 + lane];
            s.x = __expf(s.x - m); s.y = __expf(s.y - m);
            s.z = __expf(s.z - m); s.w = __expf(s.w - m);
            sv[i] = s;
            sum += s.x + s.y + s.z + s.w;
        }
        #pragma unroll
        for (int o = 16; o > 0; o >>= 1)
            sum += __shfl_xor_sync(0xffffffffu, sum, o);
        if (lane == 0) invs[q] = 1.f / sum;

        __syncthreads();   // barrier #2: fp32 reads done before overlay writes

        uint32_t* ph = phi + q * PSTR;
        uint32_t* pl = plo + q * PSTR;
        #pragma unroll
        for (int i = 0; i < 16; ++i) {
            float4 s = sv[i];
            uint32_t h0, l0, h1, l1;
            split2(s.x, s.y, h0, l0);
            split2(s.z, s.w, h1, l1);
            int pb = i * 64 + lane * 2;
            *(uint2*)(ph + pb) = make_uint2(h0, h1);
            *(uint2*)(pl + pb) = make_uint2(l0, l1);
        }
    }
    __syncthreads();   // barrier #3: p overlay complete

    // ============ Phase 3: p @ V (2-term) + coalesced attn write — no block barriers ============
    {
        const float invW = invs[warp];
        float4* attnRowW = (float4*)(attn + (rowbase + q0 + warp) * S);

        float acc[4][4];
        #pragma unroll
        for (int i = 0; i < 4; ++i)
            #pragma unroll
            for (int j = 0; j < 4; ++j) acc[i][j] = 0.f;

        #pragma unroll
        for (int p = 0; p < NTILES; ++p) {
            const int st = p & 3;

            if      (p < NTILES - 3)  cp_wait3();
            else if (p == NTILES - 3) cp_wait2();
            else if (p == NTILES - 2) cp_wait1();
            else                      cp_wait0();
            __syncwarp();

            // coalesced attn chunk: warp w writes row w, this tile's 128 cols
            {
                int pb = p * 64 + lane * 2;
                uint2 h = *(const uint2*)(phi + warp * PSTR + pb);
                uint2 l = *(const uint2*)(plo + warp * PSTR + pb);
                float2 ha = unpack_h2(h.x), la = unpack_h2(l.x);
                float2 hb = unpack_h2(h.y), lb = unpack_h2(l.y);
                attnRowW[p * 32 + lane] = make_float4(
                    (ha.x + la.x) * invW, (ha.y + la.y) * invW,
                    (hb.x + lb.x) * invW, (hb.y + lb.y) * invW);
            }

            // A fragments from p hi/lo overlay
            const int pb = p * 64 + kg * 8 + tig;
            uint32_t Ah[4], Al[4];
            Ah[0] = phi[gid * PSTR + pb];
            Ah[1] = phi[(gid + 8) * PSTR + pb];
            Ah[2] = phi[gid * PSTR + pb + 4];
            Ah[3] = phi[(gid + 8) * PSTR + pb + 4];
            Al[0] = plo[gid * PSTR + pb];
            Al[1] = plo[(gid + 8) * PSTR + pb];
            Al[2] = plo[gid * PSTR + pb + 4];
            Al[3] = plo[(gid + 8) * PSTR + pb + 4];

            const uint32_t* vs = wbuf + st * STG;
            #pragma unroll
            for (int nt = 0; nt < 4; ++nt) {
                const uint32_t* vb = vs + (nt * 2 + (gid >> 2)) * 36 + (gid & 3) * 8 + tig;
                uint32_t b0h = vb[0], b1h = vb[4];
                mma_f16(acc[nt], Ah, b0h, b1h);
                mma_f16(acc[nt], Al, b0h, b1h);
            }
            __syncwarp();
            if (p + 4 < NTILES) load_v_slice(st, p + 4);
        }
        __syncthreads();   // barrier #4: reuse per-warp region as reduce scratch

        // split-k reduce: red[kg 8][q 16][68]
        float* red = (float*)(smu + OFF_KW);
        #pragma unroll
        for (int nt = 0; nt < 4; ++nt) {
            int d = nh * 32 + nt * 8 + 2 * tig;
            *(float2*)(red + kg * 1088 + gid * 68 + d) =
                make_float2(acc[nt][0], acc[nt][1]);
            *(float2*)(red + kg * 1088 + (gid + 8) * 68 + d) =
                make_float2(acc[nt][2], acc[nt][3]);
        }
        __syncthreads();   // barrier #5

        #pragma unroll
        for (int o = t; o < TQ * D; o += NT) {
            int q = o >> 6, d = o & 63;
            float s = 0.f;
            #pragma unroll
            for (int g = 0; g < 8; ++g)
                s += red[g * 1088 + q * 68 + d];
            ctx[(rowbase + q0 + q) * D + d] = s * invs[q];
        }
    }
}

extern "C" void kernel_launch(void* const* d_in, const int* in_sizes, int n_in,
                              void* d_out, int out_size)
{
    const float* Q    = (const float*)d_in[0];
    const float* K    = (const float*)d_in[1];
    const float* V    = (const float*)d_in[2];
    const float* dist = (const float*)d_in[3];
    const int*   mask = (const int*)d_in[4];

    float* ctx  = (float*)d_out;
    float* attn = (float*)d_out + (size_t)BH * S * D;

    conv_k_kernel<<<(BH * S * D) / 256, 256>>>(K);
    {
        dim3 g(S / 64, BH);
        conv_vt_kernel<<<g, 256>>>(V);
    }

    cudaFuncSetAttribute(dist_attn_kernel,
                         cudaFuncAttributeMaxDynamicSharedMemorySize,
                         SMEM_BYTES);

    dim3 grid(S / TQ, BH);
    dist_attn_kernel<<<grid, NT, SMEM_BYTES>>>(Q, dist, mask, ctx, attn);
}

// round 16
// speedup vs baseline: 2.1083x; 1.2289x over previous
#include <cuda_runtime.h>
#include <cuda_fp16.h>
#include <cstdint>

#define BH   32
#define S    2048
#define D    64
#define TQ   16
#define NT   512
#define SCP  2052            // fp32 score row stride (floats)
#define QSP  68
#define RMP  18
#define PSTR 1036            // p hi/lo row stride (u32)
#define NTILES 16            // 128-row tiles
#define NEG_INF_F (-1e10f)
#define SCALE     (0.125f)

// smem layout (u32 units)
#define OFF_P     0            // fp32 scores 16x2052 / p hi+lo overlay
#define OFF_PLO   16576
#define OFF_KW    33152        // per-warp slice buffers: 16 warps x 4 stages x 288 u32
#define OFF_QS    51584
#define OFF_RMAX  52672
#define OFF_INVS  52960
#define SMEM_U32  52976
#define SMEM_BYTES (SMEM_U32 * 4)

#define STG 288                // per-stage u32 (hi only)
#define WBUF_STRIDE 1152       // 4 stages x 288

// pre-converted fp16 operands (hi only) in global scratch
__device__ __half g_Khi[BH * S * D];
__device__ __half g_Vthi[BH * D * S];   // transposed [bh][d][s]

__device__ __forceinline__ uint32_t pack_h2(float x, float y) {
    __half2 h = __floats2half2_rn(x, y);
    return *reinterpret_cast<uint32_t*>(&h);
}
__device__ __forceinline__ float2 unpack_h2(uint32_t u) {
    __half2 h = *reinterpret_cast<__half2*>(&u);
    return __half22float2(h);
}
__device__ __forceinline__ void split2(float x, float y, uint32_t& hi, uint32_t& lo) {
    hi = pack_h2(x, y);
    float2 hf = unpack_h2(hi);
    lo = pack_h2(x - hf.x, y - hf.y);
}

__device__ __forceinline__ void mma_f16(float* c, const uint32_t* a, uint32_t b0, uint32_t b1) {
    asm volatile(
        "mma.sync.aligned.m16n8k16.row.col.f32.f16.f16.f32 "
        "{%0,%1,%2,%3},{%4,%5,%6,%7},{%8,%9},{%0,%1,%2,%3};"
        : "+f"(c[0]), "+f"(c[1]), "+f"(c[2]), "+f"(c[3])
        : "r"(a[0]), "r"(a[1]), "r"(a[2]), "r"(a[3]), "r"(b0), "r"(b1));
}

__device__ __forceinline__ void cpa16(uint32_t* dst, const void* src) {
    uint32_t d = (uint32_t)__cvta_generic_to_shared(dst);
    asm volatile("cp.async.cg.shared.global [%0], [%1], 16;" :: "r"(d), "l"(src));
}
__device__ __forceinline__ void cp_commit() { asm volatile("cp.async.commit_group;"); }
__device__ __forceinline__ void cp_wait3() { asm volatile("cp.async.wait_group 3;" ::: "memory"); }
__device__ __forceinline__ void cp_wait2() { asm volatile("cp.async.wait_group 2;" ::: "memory"); }
__device__ __forceinline__ void cp_wait1() { asm volatile("cp.async.wait_group 1;" ::: "memory"); }
__device__ __forceinline__ void cp_wait0() { asm volatile("cp.async.wait_group 0;" ::: "memory"); }

// ---------------- pre-kernels ----------------
// vectorized: 8 floats -> 8 halves per thread (uint4 store)
__global__ void conv_k_kernel(const float* __restrict__ K) {
    int i = blockIdx.x * blockDim.x + threadIdx.x;
    const float4* src = (const float4*)K + i * 2;
    float4 a = __ldcs(src);
    float4 b = __ldcs(src + 1);
    uint4 o;
    o.x = pack_h2(a.x, a.y);
    o.y = pack_h2(a.z, a.w);
    o.z = pack_h2(b.x, b.y);
    o.w = pack_h2(b.z, b.w);
    ((uint4*)g_Khi)[i] = o;
}

__global__ void conv_vt_kernel(const float* __restrict__ V) {
    __shared__ float tile[64][65];
    int bh = blockIdx.y, s0 = blockIdx.x * 64;
    int tid = threadIdx.x;
    #pragma unroll
    for (int i = 0; i < 16; ++i) {
        int r = i * 4 + (tid >> 6), d = tid & 63;
        tile[r][d] = V[((size_t)bh * S + s0 + r) * D + d];
    }
    __syncthreads();
    #pragma unroll
    for (int i = 0; i < 16; ++i) {
        int dr = i * 4 + (tid >> 6), sc_ = tid & 63;
        g_Vthi[((size_t)bh * D + dr) * S + s0 + sc_] = __float2half_rn(tile[sc_][dr]);
    }
}

// ---------------- main kernel ----------------
__global__ __launch_bounds__(NT, 1)
void dist_attn_kernel(const float* __restrict__ Q,
                      const float* __restrict__ dist,
                      const int* __restrict__ mask,
                      float* __restrict__ ctx,
                      float* __restrict__ attn)
{
    extern __shared__ uint32_t smu[];
    uint32_t* phi  = smu + OFF_P;
    uint32_t* plo  = smu + OFF_PLO;
    float*    sc   = (float*)(smu + OFF_P);
    float*    Qs   = (float*)(smu + OFF_QS);
    float*    rmax = (float*)(smu + OFF_RMAX);
    float*    invs = (float*)(smu + OFF_INVS);

    const int t    = threadIdx.x;
    const int warp = t >> 5;
    const int lane = t & 31;
    const int gid  = lane >> 2;
    const int tig  = lane & 3;
    const int bh = blockIdx.y;
    const int q0 = blockIdx.x * TQ;
    const size_t rowbase = (size_t)bh * S;

    uint32_t* wbuf = smu + OFF_KW + warp * WBUF_STRIDE;

    const __half* Khi_b = g_Khi + (size_t)bh * S * D;

    // per-warp K slice: 8 rows x 64 halves (hi), one tile
    auto load_k_slice = [&](int stage, int tile) {
        uint32_t* dst = wbuf + stage * STG;
        #pragma unroll
        for (int i = 0; i < 2; ++i) {
            int idx = lane + i * 32;        // 0..63
            int r = idx >> 3, c = idx & 7;
            const __half* src = Khi_b + ((tile * 128 + warp * 8 + r) * D + c * 8);
            cpa16(dst + r * 36 + c * 4, src);
        }
        cp_commit();
    };

    // prologue: 4-deep
    load_k_slice(0, 0);
    load_k_slice(1, 1);
    load_k_slice(2, 2);
    load_k_slice(3, 3);

    if (t < 256) {
        const float4 v = ((const float4*)(Q + (rowbase + q0) * D))[t];
        int qr = t >> 4, d4 = t & 15;
        *(float4*)(Qs + qr * QSP + d4 * 4) = v;
    }
    __syncthreads();

    // Q A-fragments (fp16 hi/lo), 4 k16-chunks
    uint32_t qa_hi[4][4], qa_lo[4][4];
    #pragma unroll
    for (int c = 0; c < 4; ++c) {
        const float* qg  = Qs + gid * QSP       + c * 16 + 2 * tig;
        const float* qg8 = Qs + (gid + 8) * QSP + c * 16 + 2 * tig;
        split2(qg[0],  qg[1],  qa_hi[c][0], qa_lo[c][0]);
        split2(qg8[0], qg8[1], qa_hi[c][1], qa_lo[c][1]);
        split2(qg[8],  qg[9],  qa_hi[c][2], qa_lo[c][2]);
        split2(qg8[8], qg8[9], qa_hi[c][3], qa_lo[c][3]);
    }

    // ============ Phase 1: QK^T (2-term) + dist/mask/scale + row-max — no block barriers ============
    const size_t rg0 = (rowbase + q0 + gid) * S;
    const size_t rg8 = (rowbase + q0 + gid + 8) * S;
    const int colw = warp * 8 + 2 * tig;

    // 3-deep dist/mask register pipeline (streaming loads — evict-first)
    float2 dd0[3], dd1[3];
    int2   mm0[3], mm1[3];
    #pragma unroll
    for (int p = 0; p < 3; ++p) {
        int col = p * 128 + colw;
        dd0[p] = __ldcs((const float2*)(dist + rg0 + col));
        dd1[p] = __ldcs((const float2*)(dist + rg8 + col));
        mm0[p] = __ldcs((const int2*)(mask + rg0 + col));
        mm1[p] = __ldcs((const int2*)(mask + rg8 + col));
    }

    float m0 = -3.4e38f, m1 = -3.4e38f;
    #pragma unroll
    for (int p = 0; p < NTILES; ++p) {
        const int st = p & 3;
        const int rp = p % 3;

        float2 d0 = dd0[rp], d1 = dd1[rp];
        int2   k0 = mm0[rp], k1 = mm1[rp];
        if (p + 3 < NTILES) {
            int col = (p + 3) * 128 + colw;
            dd0[rp] = __ldcs((const float2*)(dist + rg0 + col));
            dd1[rp] = __ldcs((const float2*)(dist + rg8 + col));
            mm0[rp] = __ldcs((const int2*)(mask + rg0 + col));
            mm1[rp] = __ldcs((const int2*)(mask + rg8 + col));
        }

        if      (p < NTILES - 3)  cp_wait3();
        else if (p == NTILES - 3) cp_wait2();
        else if (p == NTILES - 2) cp_wait1();
        else                      cp_wait0();
        __syncwarp();

        float aHH[4] = {0,0,0,0}, aLH[4] = {0,0,0,0};
        const uint32_t* kb = wbuf + st * STG + gid * 36 + tig;
        #pragma unroll
        for (int c = 0; c < 4; ++c) {
            uint32_t b0h = kb[c * 8], b1h = kb[c * 8 + 4];
            mma_f16(aHH, qa_hi[c], b0h, b1h);
            mma_f16(aLH, qa_lo[c], b0h, b1h);
        }
        __syncwarp();
        if (p + 4 < NTILES) load_k_slice(st, p + 4);

        float s0 = aHH[0] + aLH[0];
        float s1 = aHH[1] + aLH[1];
        float s2 = aHH[2] + aLH[2];
        float s3 = aHH[3] + aLH[3];
        s0 = k0.x ? NEG_INF_F : d0.x * s0 * SCALE;
        s1 = k0.y ? NEG_INF_F : d0.y * s1 * SCALE;
        s2 = k1.x ? NEG_INF_F : d1.x * s2 * SCALE;
        s3 = k1.y ? NEG_INF_F : d1.y * s3 * SCALE;
        m0 = fmaxf(m0, fmaxf(s0, s1));
        m1 = fmaxf(m1, fmaxf(s2, s3));
        const int col = p * 128 + colw;
        *(float2*)(sc + gid * SCP + col)       = make_float2(s0, s1);
        *(float2*)(sc + (gid + 8) * SCP + col) = make_float2(s2, s3);
    }

    // V^T slice prefetch for tiles 0..3 — issue BEFORE rowmax reduce, overlaps softmax
    const int kg = warp & 7;
    const int nh = warp >> 3;
    const __half* Vthi_b = g_Vthi + ((size_t)bh * D + nh * 32) * S;
    auto load_v_slice = [&](int stage, int tile) {
        uint32_t* dst = wbuf + stage * STG;
        int pcol = tile * 128 + kg * 16;
        #pragma unroll
        for (int i = 0; i < 2; ++i) {
            int idx = lane + i * 32;   // 0..63
            int r = idx >> 1, c = idx & 1;
            const __half* src = Vthi_b + ((size_t)r * S + pcol + c * 8);
            cpa16(dst + (r >> 2) * 36 + (r & 3) * 8 + c * 4, src);
        }
        cp_commit();
    };
    load_v_slice(0, 0);
    load_v_slice(1, 1);
    load_v_slice(2, 2);
    load_v_slice(3, 3);

    #pragma unroll
    for (int o = 1; o <= 2; o <<= 1) {
        m0 = fmaxf(m0, __shfl_xor_sync(0xffffffffu, m0, o));
        m1 = fmaxf(m1, __shfl_xor_sync(0xffffffffu, m1, o));
    }
    if (tig == 0) {
        rmax[warp * RMP + gid]     = m0;
        rmax[warp * RMP + gid + 8] = m1;
    }
    __syncthreads();   // barrier #1: scores complete

    // ============ Phase 2: exp + row-sum, store p as fp16 hi/lo overlay ============
    {
        const int q = warp;
        float4* scRow = (float4*)(sc + q * SCP);

        float m = (lane < 16) ? rmax[lane * RMP + q] : -3.4e38f;
        #pragma unroll
        for (int o = 16; o > 0; o >>= 1)
            m = fmaxf(m, __shfl_xor_sync(0xffffffffu, m, o));

        float4 sv[16];
        float sum = 0.f;
        #pragma unroll
        for (int i = 0; i < 16; ++i) {
            float4 s = scRow[i * 32 + lane];
            s.x = __expf(s.x - m); s.y = __expf(s.y - m);
            s.z = __expf(s.z - m); s.w = __expf(s.w - m);
            sv[i] = s;
            sum += s.x + s.y + s.z + s.w;
        }
        #pragma unroll
        for (int o = 16; o > 0; o >>= 1)
            sum += __shfl_xor_sync(0xffffffffu, sum, o);
        if (lane == 0) invs[q] = 1.f / sum;

        __syncthreads();   // barrier #2: fp32 reads done before overlay writes

        uint32_t* ph = phi + q * PSTR;
        uint32_t* pl = plo + q * PSTR;
        #pragma unroll
        for (int i = 0; i < 16; ++i) {
            float4 s = sv[i];
            uint32_t h0, l0, h1, l1;
            split2(s.x, s.y, h0, l0);
            split2(s.z, s.w, h1, l1);
            int pb = i * 64 + lane * 2;
            *(uint2*)(ph + pb) = make_uint2(h0, h1);
            *(uint2*)(pl + pb) = make_uint2(l0, l1);
        }
    }
    __syncthreads();   // barrier #3: p overlay complete

    // ============ Phase 3: p @ V (2-term) + coalesced streaming attn write ============
    {
        const float invW = invs[warp];
        float4* attnRowW = (float4*)(attn + (rowbase + q0 + warp) * S);

        float acc[4][4];
        #pragma unroll
        for (int i = 0; i < 4; ++i)
            #pragma unroll
            for (int j = 0; j < 4; ++j) acc[i][j] = 0.f;

        #pragma unroll
        for (int p = 0; p < NTILES; ++p) {
            const int st = p & 3;

            if      (p < NTILES - 3)  cp_wait3();
            else if (p == NTILES - 3) cp_wait2();
            else if (p == NTILES - 2) cp_wait1();
            else                      cp_wait0();
            __syncwarp();

            // coalesced attn chunk: warp w writes row w, this tile's 128 cols
            {
                int pb = p * 64 + lane * 2;
                uint2 h = *(const uint2*)(phi + warp * PSTR + pb);
                uint2 l = *(const uint2*)(plo + warp * PSTR + pb);
                float2 ha = unpack_h2(h.x), la = unpack_h2(l.x);
                float2 hb = unpack_h2(h.y), lb = unpack_h2(l.y);
                __stcs(attnRowW + p * 32 + lane, make_float4(
                    (ha.x + la.x) * invW, (ha.y + la.y) * invW,
                    (hb.x + lb.x) * invW, (hb.y + lb.y) * invW));
            }

            // A fragments from p hi/lo overlay
            const int pb = p * 64 + kg * 8 + tig;
            uint32_t Ah[4], Al[4];
            Ah[0] = phi[gid * PSTR + pb];
            Ah[1] = phi[(gid + 8) * PSTR + pb];
            Ah[2] = phi[gid * PSTR + pb + 4];
            Ah[3] = phi[(gid + 8) * PSTR + pb + 4];
            Al[0] = plo[gid * PSTR + pb];
            Al[1] = plo[(gid + 8) * PSTR + pb];
            Al[2] = plo[gid * PSTR + pb + 4];
            Al[3] = plo[(gid + 8) * PSTR + pb + 4];

            const uint32_t* vs = wbuf + st * STG;
            #pragma unroll
            for (int nt = 0; nt < 4; ++nt) {
                const uint32_t* vb = vs + (nt * 2 + (gid >> 2)) * 36 + (gid & 3) * 8 + tig;
                uint32_t b0h = vb[0], b1h = vb[4];
                mma_f16(acc[nt], Ah, b0h, b1h);
                mma_f16(acc[nt], Al, b0h, b1h);
            }
            __syncwarp();
            if (p + 4 < NTILES) load_v_slice(st, p + 4);
        }
        __syncthreads();   // barrier #4: reuse per-warp region as reduce scratch

        // split-k reduce: red[kg 8][q 16][68]
        float* red = (float*)(smu + OFF_KW);
        #pragma unroll
        for (int nt = 0; nt < 4; ++nt) {
            int d = nh * 32 + nt * 8 + 2 * tig;
            *(float2*)(red + kg * 1088 + gid * 68 + d) =
                make_float2(acc[nt][0], acc[nt][1]);
            *(float2*)(red + kg * 1088 + (gid + 8) * 68 + d) =
                make_float2(acc[nt][2], acc[nt][3]);
        }
        __syncthreads();   // barrier #5

        #pragma unroll
        for (int o = t; o < TQ * D; o += NT) {
            int q = o >> 6, d = o & 63;
            float s = 0.f;
            #pragma unroll
            for (int g = 0; g < 8; ++g)
                s += red[g * 1088 + q * 68 + d];
            ctx[(rowbase + q0 + q) * D + d] = s * invs[q];
        }
    }
}

extern "C" void kernel_launch(void* const* d_in, const int* in_sizes, int n_in,
                              void* d_out, int out_size)
{
    const float* Q    = (const float*)d_in[0];
    const float* K    = (const float*)d_in[1];
    const float* V    = (const float*)d_in[2];
    const float* dist = (const float*)d_in[3];
    const int*   mask = (const int*)d_in[4];

    float* ctx  = (float*)d_out;
    float* attn = (float*)d_out + (size_t)BH * S * D;

    conv_k_kernel<<<(BH * S * D) / (256 * 8), 256>>>(K);
    {
        dim3 g(S / 64, BH);
        conv_vt_kernel<<<g, 256>>>(V);
    }

    cudaFuncSetAttribute(dist_attn_kernel,
                         cudaFuncAttributeMaxDynamicSharedMemorySize,
                         SMEM_BYTES);

    dim3 grid(S / TQ, BH);
    dist_attn_kernel<<<grid, NT, SMEM_BYTES>>>(Q, dist, mask, ctx, attn);
}